// round 16
// baseline (speedup 1.0000x reference)
#include <cuda_runtime.h>

#define T_LEN  2048
#define HID    15
#define EDIM   300
#define G4     60
#define TPAIR  (T_LEN / 2)
#define TPPAD  (TPAIR + 4)   // pad so prefetch never needs a branch

// Packed pre-gates: for each sequence s, timestep-pair p, lane l:
//   g_pre4[s][p][l] = float4( A(2p,l), B(2p,l), A(2p+1,l), B(2p+1,l) )
// where A = pre-scaled i-row (lane<16) / f-row (lane>=16),
//       B = pre-scaled g-row (lane<16) / o-row (lane>=16).
// i/f/o rows ×0.5 (sigmoid via 0.5*tanh(0.5x)+0.5), g rows ×1.0.
// Lanes 15 and 31 are written as zeros (their weights are zero).
__device__ float4 g_pre4[2 * TPPAD * 32];

// ---------------------------------------------------------------------------
// Kernel 1: input projection + bias, scaled, scattered into g_pre4.
// ---------------------------------------------------------------------------
__global__ void precompute_kernel(const int* __restrict__ s1,
                                  const int* __restrict__ s2,
                                  const float* __restrict__ emb,
                                  const float* __restrict__ W_ih,
                                  const float* __restrict__ b_ih,
                                  const float* __restrict__ b_hh) {
    __shared__ float4 semb[EDIM / 4];

    const int bid = blockIdx.x;
    const int s   = bid >> 11;
    const int t   = bid & (T_LEN - 1);
    const int tok = (s == 0) ? s1[t] : s2[t];

    const float4* erow = reinterpret_cast<const float4*>(emb + (long long)tok * EDIM);
    for (int i = threadIdx.x; i < EDIM / 4; i += blockDim.x)
        semb[i] = erow[i];
    __syncthreads();

    float* base = reinterpret_cast<float*>(g_pre4);
    const int j = threadIdx.x;   // 0..63

    if (j < G4) {
        const float4* wrow = reinterpret_cast<const float4*>(W_ih + j * EDIM);
        float a0 = 0.f, a1 = 0.f, a2 = 0.f, a3 = 0.f;
        #pragma unroll 5
        for (int e = 0; e < EDIM / 4; e++) {
            float4 wv = wrow[e];
            float4 xv = semb[e];
            a0 = fmaf(wv.x, xv.x, a0);
            a1 = fmaf(wv.y, xv.y, a1);
            a2 = fmaf(wv.z, xv.z, a2);
            a3 = fmaf(wv.w, xv.w, a3);
        }
        const float scale = (j >= 30 && j < 45) ? 1.0f : 0.5f;  // g rows: 1.0
        float acc = scale * (b_ih[j] + b_hh[j] + ((a0 + a1) + (a2 + a3)));

        // gate row -> (lane, slot):  i: (j,0)  f: (16+j-15,0)
        //                            g: (j-30,1) o: (16+j-45,1)
        int lane, slot;
        if (j < 15)      { lane = j;           slot = 0; }
        else if (j < 30) { lane = 16 + j - 15; slot = 0; }
        else if (j < 45) { lane = j - 30;      slot = 1; }
        else             { lane = 16 + j - 45; slot = 1; }

        base[(((s * TPPAD + (t >> 1)) * 32) + lane) * 4 + (t & 1) * 2 + slot] = acc;
    } else {
        // j = 60..63: zero-fill lanes 15 and 31 (keeps NaN out of dead slots)
        int lane = (j < 62) ? 15 : 31;
        int slot = j & 1;
        base[(((s * TPPAD + (t >> 1)) * 32) + lane) * 4 + (t & 1) * 2 + slot] = 0.0f;
    }
}

// Hardware tanh (single MUFU.TANH)
__device__ __forceinline__ float tanhfast(float x) {
    float y; asm("tanh.approx.f32 %0, %1;" : "=f"(y) : "f"(x)); return y;
}

// ---------------------------------------------------------------------------
// Kernel 2: both LSTM recurrences (1 warp each, same block) + fused MLP.
// Lane k<15:  gates i_k, g_k (pre-scaled); holds state h_k, c_k.
// Lane 16+k:  gates f_k, o_k (pre-scaled); FINISHED activations shfl'd down.
// a/e dot FMAs INTERLEAVED so aa and ab finish ~together (balances the two
// MUFU+shfl pipelines; o-path no longer the tail). Activations applied
// before the shfl with one branchless FFMA per MUFU result.
// h broadcast PIPELINED: STS + 4x LDS.128 at the BOTTOM of each step.
// ---------------------------------------------------------------------------
__global__ __launch_bounds__(64, 1)
void recurrence_kernel(const float* __restrict__ W_hh,
                       const float* __restrict__ W1,
                       const float* __restrict__ b1,
                       const float* __restrict__ W2,
                       const float* __restrict__ b2,
                       const float* __restrict__ h1_0,
                       const float* __restrict__ c1_0,
                       const float* __restrict__ h2_0,
                       const float* __restrict__ c2_0,
                       float* __restrict__ out) {
    const int tid  = threadIdx.x;
    const int w    = tid >> 5;
    const int lane = tid & 31;

    __shared__ __align__(16) float shh[2][32];   // per-warp h slots
    __shared__ float sh_h[2][16];
    __shared__ float sh_hidden[25];

    const bool lowhalf = (lane < 16);
    const int  sub     = lowhalf ? lane : lane - 16;
    const bool valid   = (sub < HID);

    const int ia = valid ? (lowhalf ? sub      : 15 + sub) : 0;  // i / f
    const int ib = valid ? (lowhalf ? 30 + sub : 45 + sub) : 0;  // g / o

    // Pre-scaled recurrent rows (16-wide, slot 15 = 0 kills junk h[15])
    const float sB = lowhalf ? 1.0f : 0.5f;   // g ×1.0, o ×0.5
    float Wa[16], Wb[16];
    #pragma unroll
    for (int m = 0; m < HID; m++) {
        Wa[m] = valid ? 0.5f * W_hh[ia * HID + m] : 0.0f;
        Wb[m] = valid ? sB   * W_hh[ib * HID + m] : 0.0f;
    }
    Wa[15] = 0.0f; Wb[15] = 0.0f;

    // act_b transform: low (g): identity; high (o): sigmoid reconstruction
    const float mb = lowhalf ? 1.0f : 0.5f;
    const float cb = lowhalf ? 0.0f : 0.5f;

    const float* h0p = (w == 0) ? h1_0 : h2_0;
    const float* c0p = (w == 0) ? c1_0 : c2_0;
    float cval = (lowhalf && valid) ? c0p[sub] : 0.0f;
    float hval = (lowhalf && valid) ? h0p[sub] : 0.0f;

    shh[w][lane] = hval;
    __syncthreads();

    const float4* s4 = reinterpret_cast<const float4*>(shh[w]);
    float4 H0 = s4[0], H1 = s4[1], H2 = s4[2], H3 = s4[3];

    // packed pre pointer: one float4 per 2 steps, stride 32 float4s per pair
    const float4* pp = g_pre4 + (w * TPPAD) * 32 + lane;

    // two-pair (4-step) register prefetch; pad absorbs overrun
    float4 P0 = __ldg(pp);
    float4 P1 = __ldg(pp + 32);
    pp += 64;

    #pragma unroll 2
    for (int p = 0; p < TPAIR; p++) {
        const float4 P = P0;
        P0 = P1;
        P1 = __ldg(pp);
        pp += 32;

        #pragma unroll
        for (int half = 0; half < 2; half++) {
            const float pa = half ? P.z : P.x;
            const float pb = half ? P.w : P.y;

            // ---- interleaved dot products (aa and ab finish together) ----
            float a0 = fmaf(Wa[0],  H0.x, pa);  float e0 = fmaf(Wb[0],  H0.x, pb);
            float a1 = Wa[1] * H0.y;            float e1 = Wb[1] * H0.y;
            float a2 = Wa[2] * H0.z;            float e2 = Wb[2] * H0.z;
            float a3 = Wa[3] * H0.w;            float e3 = Wb[3] * H0.w;
            a0 = fmaf(Wa[4],  H1.x, a0);        e0 = fmaf(Wb[4],  H1.x, e0);
            a1 = fmaf(Wa[5],  H1.y, a1);        e1 = fmaf(Wb[5],  H1.y, e1);
            a2 = fmaf(Wa[6],  H1.z, a2);        e2 = fmaf(Wb[6],  H1.z, e2);
            a3 = fmaf(Wa[7],  H1.w, a3);        e3 = fmaf(Wb[7],  H1.w, e3);
            a0 = fmaf(Wa[8],  H2.x, a0);        e0 = fmaf(Wb[8],  H2.x, e0);
            a1 = fmaf(Wa[9],  H2.y, a1);        e1 = fmaf(Wb[9],  H2.y, e1);
            a2 = fmaf(Wa[10], H2.z, a2);        e2 = fmaf(Wb[10], H2.z, e2);
            a3 = fmaf(Wa[11], H2.w, a3);        e3 = fmaf(Wb[11], H2.w, e3);
            a0 = fmaf(Wa[12], H3.x, a0);        e0 = fmaf(Wb[12], H3.x, e0);
            a1 = fmaf(Wa[13], H3.y, a1);        e1 = fmaf(Wb[13], H3.y, e1);
            a2 = fmaf(Wa[14], H3.z, a2);        e2 = fmaf(Wb[14], H3.z, e2);

            float aa = (a0 + a1) + (a2 + a3);
            float ta = tanhfast(aa);                 // i (low) / f (high) raw
            float ab = (e0 + e1) + (e2 + e3);
            float tb = tanhfast(ab);                 // g (low) / o (high) raw

            // finished activations BEFORE the shfl (one FFMA each, all lanes)
            float act_a = fmaf(0.5f, ta, 0.5f);      // sigmoid: i (low), f (high)
            float fv = __shfl_down_sync(0xffffffffu, act_a, 16);  // σ(f)
            float act_b = fmaf(mb, tb, cb);          // g (low), σ(o) (high)
            float ov = __shfl_down_sync(0xffffffffu, act_b, 16);  // σ(o)

            float ig = act_a * act_b;                // σ(i)·g on low lanes
            cval = fmaf(fv, cval, ig);               // c' = f*c + i*g
            float tc = tanhfast(cval);
            hval = ov * tc;                          // h' = o * tanh(c')

            // pipelined broadcast: STS then LDS for next step
            shh[w][lane] = hval;
            H0 = s4[0]; H1 = s4[1]; H2 = s4[2]; H3 = s4[3];
        }
    }

    // ---- fused final MLP ----
    if (lowhalf && valid) sh_h[w][sub] = hval;
    __syncthreads();

    if (tid < 25) {
        const float* w1r = W1 + tid * (5 * HID);
        float acc = b1[tid];
        #pragma unroll
        for (int kk = 0; kk < HID; kk++) {
            float v1 = sh_h[0][kk];
            float v2 = sh_h[1][kk];
            acc = fmaf(w1r[kk],           v1,               acc);
            acc = fmaf(w1r[HID + kk],     fabsf(v1 - v2),   acc);
            acc = fmaf(w1r[2 * HID + kk], v2,               acc);
            acc = fmaf(w1r[3 * HID + kk], v1 * v2,          acc);
            acc = fmaf(w1r[4 * HID + kk], 0.5f * (v1 + v2), acc);
        }
        sh_hidden[tid] = acc;
    }
    __syncthreads();

    if (tid < 2) {
        float acc = b2[tid];
        #pragma unroll
        for (int j = 0; j < 25; j++)
            acc = fmaf(W2[tid * 25 + j], sh_hidden[j], acc);
        out[tid] = acc;
    }
}

extern "C" void kernel_launch(void* const* d_in, const int* in_sizes, int n_in,
                              void* d_out, int out_size) {
    const int*   s1   = (const int*)  d_in[0];
    const int*   s2   = (const int*)  d_in[1];
    const float* emb  = (const float*)d_in[2];
    const float* W_ih = (const float*)d_in[3];
    const float* W_hh = (const float*)d_in[4];
    const float* b_ih = (const float*)d_in[5];
    const float* b_hh = (const float*)d_in[6];
    const float* W1   = (const float*)d_in[7];
    const float* b1   = (const float*)d_in[8];
    const float* W2   = (const float*)d_in[9];
    const float* b2   = (const float*)d_in[10];
    const float* h1_0 = (const float*)d_in[11];
    const float* c1_0 = (const float*)d_in[12];
    const float* h2_0 = (const float*)d_in[13];
    const float* c2_0 = (const float*)d_in[14];
    float* out = (float*)d_out;

    precompute_kernel<<<2 * T_LEN, 64>>>(s1, s2, emb, W_ih, b_ih, b_hh);
    recurrence_kernel<<<1, 64>>>(W_hh, W1, b1, W2, b2,
                                 h1_0, c1_0, h2_0, c2_0, out);
}

// round 17
// speedup vs baseline: 1.1262x; 1.1262x over previous
#include <cuda_runtime.h>

#define T_LEN  2048
#define HID    15
#define EDIM   300
#define G4     60
#define BTOK   8
#define TPAIR  (T_LEN / 2)
#define TPPAD  (TPAIR + 4)   // pad so prefetch never needs a branch

// Packed pre-gates: for each sequence s, timestep-pair p, lane l:
//   g_pre4[s][p][l] = float4( A(2p,l), B(2p,l), A(2p+1,l), B(2p+1,l) )
// where A = pre-scaled i-row (lane<16) / f-row (lane>=16),
//       B = pre-scaled g-row (lane<16) / o-row (lane>=16).
// i/f/o rows ×0.5 (sigmoid via 0.5*tanh(0.5x)+0.5), g rows ×1.0.
// Lanes 15 and 31 are written as zeros (their weights are zero).
__device__ float4 g_pre4[2 * TPPAD * 32];

// ---------------------------------------------------------------------------
// Kernel 1: input projection, 8 tokens per block.
// 8 emb rows staged in smem; each W_ih float4 is loaded ONCE per 8 tokens
// (8x less L1 traffic); smem reads are warp-uniform -> broadcast (free-ish).
// ---------------------------------------------------------------------------
__global__ void precompute_kernel(const int* __restrict__ s1,
                                  const int* __restrict__ s2,
                                  const float* __restrict__ emb,
                                  const float* __restrict__ W_ih,
                                  const float* __restrict__ b_ih,
                                  const float* __restrict__ b_hh) {
    __shared__ __align__(16) float semb[BTOK][EDIM];   // 9.6 KB

    const int bid = blockIdx.x;          // 0..511
    const int s   = bid >> 8;            // sequence
    const int t0  = (bid & 255) * BTOK;  // first token of this block
    const int* seq = (s == 0) ? s1 : s2;
    const int tid = threadIdx.x;

    // stage 8 embedding rows (600 float4 across 64 threads)
    for (int idx = tid; idx < BTOK * (EDIM / 4); idx += 64) {
        int row = idx / (EDIM / 4);
        int c   = idx - row * (EDIM / 4);
        int tok = seq[t0 + row];
        reinterpret_cast<float4*>(semb[row])[c] =
            reinterpret_cast<const float4*>(emb + (long long)tok * EDIM)[c];
    }
    __syncthreads();

    float* base = reinterpret_cast<float*>(g_pre4);
    const int j = tid;                   // gate row

    if (j < G4) {
        const float4* wrow = reinterpret_cast<const float4*>(W_ih + j * EDIM);
        float acc[BTOK];
        #pragma unroll
        for (int k = 0; k < BTOK; k++) acc[k] = 0.0f;

        #pragma unroll 3
        for (int e = 0; e < EDIM / 4; e++) {
            float4 wv = __ldg(wrow + e);           // one W load per 8 tokens
            #pragma unroll
            for (int k = 0; k < BTOK; k++) {
                float4 xv = reinterpret_cast<const float4*>(semb[k])[e];  // broadcast
                acc[k] = fmaf(wv.x, xv.x, acc[k]);
                acc[k] = fmaf(wv.y, xv.y, acc[k]);
                acc[k] = fmaf(wv.z, xv.z, acc[k]);
                acc[k] = fmaf(wv.w, xv.w, acc[k]);
            }
        }

        const float scale = (j >= 30 && j < 45) ? 1.0f : 0.5f;  // g rows: 1.0
        const float bias  = b_ih[j] + b_hh[j];

        // gate row -> (lane, slot):  i: (j,0)  f: (16+j-15,0)
        //                            g: (j-30,1) o: (16+j-45,1)
        int lane, slot;
        if (j < 15)      { lane = j;           slot = 0; }
        else if (j < 30) { lane = 16 + j - 15; slot = 0; }
        else if (j < 45) { lane = j - 30;      slot = 1; }
        else             { lane = 16 + j - 45; slot = 1; }

        #pragma unroll
        for (int k = 0; k < BTOK; k++) {
            int t = t0 + k;
            base[(((s * TPPAD + (t >> 1)) * 32) + lane) * 4 + (t & 1) * 2 + slot]
                = scale * (bias + acc[k]);
        }
    } else {
        // threads 60..63: zero-fill lanes 15/31 (keeps NaN out of dead slots)
        int z    = j - 60;
        int lane = (z < 2) ? 15 : 31;
        int slot = z & 1;
        #pragma unroll
        for (int k = 0; k < BTOK; k++) {
            int t = t0 + k;
            base[(((s * TPPAD + (t >> 1)) * 32) + lane) * 4 + (t & 1) * 2 + slot] = 0.0f;
        }
    }
}

// Hardware tanh (single MUFU.TANH)
__device__ __forceinline__ float tanhfast(float x) {
    float y; asm("tanh.approx.f32 %0, %1;" : "=f"(y) : "f"(x)); return y;
}

// ---------------------------------------------------------------------------
// Kernel 2: both LSTM recurrences (1 warp each, same block) + fused MLP.
// EXACT best-known body (225.8us): critical-path-first a-tree, MUFU asap,
// e-tree in the shfl shadow, post-shfl sigmoid reconstruction, pipelined
// STS + 4x LDS.128 broadcast at the step bottom, packed float4 pre loads.
// ---------------------------------------------------------------------------
__global__ __launch_bounds__(64, 1)
void recurrence_kernel(const float* __restrict__ W_hh,
                       const float* __restrict__ W1,
                       const float* __restrict__ b1,
                       const float* __restrict__ W2,
                       const float* __restrict__ b2,
                       const float* __restrict__ h1_0,
                       const float* __restrict__ c1_0,
                       const float* __restrict__ h2_0,
                       const float* __restrict__ c2_0,
                       float* __restrict__ out) {
    const int tid  = threadIdx.x;
    const int w    = tid >> 5;
    const int lane = tid & 31;

    __shared__ __align__(16) float shh[2][32];   // per-warp h slots
    __shared__ float sh_h[2][16];
    __shared__ float sh_hidden[25];

    const bool lowhalf = (lane < 16);
    const int  sub     = lowhalf ? lane : lane - 16;
    const bool valid   = (sub < HID);

    const int ia = valid ? (lowhalf ? sub      : 15 + sub) : 0;  // i / f
    const int ib = valid ? (lowhalf ? 30 + sub : 45 + sub) : 0;  // g / o

    // Pre-scaled recurrent rows (16-wide, slot 15 = 0 kills junk h[15])
    const float sB = lowhalf ? 1.0f : 0.5f;   // g ×1.0, o ×0.5
    float Wa[16], Wb[16];
    #pragma unroll
    for (int m = 0; m < HID; m++) {
        Wa[m] = valid ? 0.5f * W_hh[ia * HID + m] : 0.0f;
        Wb[m] = valid ? sB   * W_hh[ib * HID + m] : 0.0f;
    }
    Wa[15] = 0.0f; Wb[15] = 0.0f;

    const float* h0p = (w == 0) ? h1_0 : h2_0;
    const float* c0p = (w == 0) ? c1_0 : c2_0;
    float cval = (lowhalf && valid) ? c0p[sub] : 0.0f;
    float hval = (lowhalf && valid) ? h0p[sub] : 0.0f;

    shh[w][lane] = hval;
    __syncthreads();

    const float4* s4 = reinterpret_cast<const float4*>(shh[w]);
    float4 H0 = s4[0], H1 = s4[1], H2 = s4[2], H3 = s4[3];

    // packed pre pointer: one float4 per 2 steps, stride 32 float4s per pair
    const float4* pp = g_pre4 + (w * TPPAD) * 32 + lane;

    // two-pair (4-step) register prefetch; pad absorbs overrun
    float4 P0 = __ldg(pp);
    float4 P1 = __ldg(pp + 32);
    pp += 64;

    #pragma unroll 2
    for (int p = 0; p < TPAIR; p++) {
        const float4 P = P0;
        P0 = P1;
        P1 = __ldg(pp);
        pp += 32;

        #pragma unroll
        for (int half = 0; half < 2; half++) {
            const float pa = half ? P.z : P.x;
            const float pb = half ? P.w : P.y;

            // ---- critical path first: aa (i low / f high) ----
            float a0 = fmaf(Wa[0],  H0.x, pa);
            float a1 = Wa[1] * H0.y;
            float a2 = Wa[2] * H0.z;
            float a3 = Wa[3] * H0.w;
            a0 = fmaf(Wa[4],  H1.x, a0);
            a1 = fmaf(Wa[5],  H1.y, a1);
            a2 = fmaf(Wa[6],  H1.z, a2);
            a3 = fmaf(Wa[7],  H1.w, a3);
            a0 = fmaf(Wa[8],  H2.x, a0);
            a1 = fmaf(Wa[9],  H2.y, a1);
            a2 = fmaf(Wa[10], H2.z, a2);
            a3 = fmaf(Wa[11], H2.w, a3);
            a0 = fmaf(Wa[12], H3.x, a0);
            a1 = fmaf(Wa[13], H3.y, a1);
            a2 = fmaf(Wa[14], H3.z, a2);
            float aa = (a0 + a1) + (a2 + a3);

            float ta = tanhfast(aa);                             // MUFU asap
            float taf = __shfl_down_sync(0xffffffffu, ta, 16);   // raw f

            // ---- ab (g low / o high) hides in the shfl shadow ----
            float e0 = fmaf(Wb[0],  H0.x, pb);
            float e1 = Wb[1] * H0.y;
            float e2 = Wb[2] * H0.z;
            float e3 = Wb[3] * H0.w;
            e0 = fmaf(Wb[4],  H1.x, e0);
            e1 = fmaf(Wb[5],  H1.y, e1);
            e2 = fmaf(Wb[6],  H1.z, e2);
            e3 = fmaf(Wb[7],  H1.w, e3);
            e0 = fmaf(Wb[8],  H2.x, e0);
            e1 = fmaf(Wb[9],  H2.y, e1);
            e2 = fmaf(Wb[10], H2.z, e2);
            e3 = fmaf(Wb[11], H2.w, e3);
            e0 = fmaf(Wb[12], H3.x, e0);
            e1 = fmaf(Wb[13], H3.y, e1);
            e2 = fmaf(Wb[14], H3.z, e2);
            float ab = (e0 + e1) + (e2 + e3);

            float tb = tanhfast(ab);                             // g / o raw
            float tbo = __shfl_down_sync(0xffffffffu, tb, 16);   // raw o

            // ig = sigmoid(i)*g = ta*(0.5*tb) + 0.5*tb
            float tbh = 0.5f * tb;
            float ig  = fmaf(ta, tbh, tbh);

            float fv = fmaf(0.5f, taf, 0.5f);    // sigmoid(f)
            cval = fmaf(fv, cval, ig);           // c' = f*c + i*g
            float ov = fmaf(0.5f, tbo, 0.5f);    // sigmoid(o)
            float tc = tanhfast(cval);
            hval = ov * tc;                      // h' = o * tanh(c')

            // pipelined broadcast: STS then LDS for next step
            shh[w][lane] = hval;
            H0 = s4[0]; H1 = s4[1]; H2 = s4[2]; H3 = s4[3];
        }
    }

    // ---- fused final MLP ----
    if (lowhalf && valid) sh_h[w][sub] = hval;
    __syncthreads();

    if (tid < 25) {
        const float* w1r = W1 + tid * (5 * HID);
        float acc = b1[tid];
        #pragma unroll
        for (int kk = 0; kk < HID; kk++) {
            float v1 = sh_h[0][kk];
            float v2 = sh_h[1][kk];
            acc = fmaf(w1r[kk],           v1,               acc);
            acc = fmaf(w1r[HID + kk],     fabsf(v1 - v2),   acc);
            acc = fmaf(w1r[2 * HID + kk], v2,               acc);
            acc = fmaf(w1r[3 * HID + kk], v1 * v2,          acc);
            acc = fmaf(w1r[4 * HID + kk], 0.5f * (v1 + v2), acc);
        }
        sh_hidden[tid] = acc;
    }
    __syncthreads();

    if (tid < 2) {
        float acc = b2[tid];
        #pragma unroll
        for (int j = 0; j < 25; j++)
            acc = fmaf(W2[tid * 25 + j], sh_hidden[j], acc);
        out[tid] = acc;
    }
}

extern "C" void kernel_launch(void* const* d_in, const int* in_sizes, int n_in,
                              void* d_out, int out_size) {
    const int*   s1   = (const int*)  d_in[0];
    const int*   s2   = (const int*)  d_in[1];
    const float* emb  = (const float*)d_in[2];
    const float* W_ih = (const float*)d_in[3];
    const float* W_hh = (const float*)d_in[4];
    const float* b_ih = (const float*)d_in[5];
    const float* b_hh = (const float*)d_in[6];
    const float* W1   = (const float*)d_in[7];
    const float* b1   = (const float*)d_in[8];
    const float* W2   = (const float*)d_in[9];
    const float* b2   = (const float*)d_in[10];
    const float* h1_0 = (const float*)d_in[11];
    const float* c1_0 = (const float*)d_in[12];
    const float* h2_0 = (const float*)d_in[13];
    const float* c2_0 = (const float*)d_in[14];
    float* out = (float*)d_out;

    precompute_kernel<<<2 * T_LEN / BTOK, 64>>>(s1, s2, emb, W_ih, b_ih, b_hh);
    recurrence_kernel<<<1, 64>>>(W_hh, W1, b1, W2, b2,
                                 h1_0, c1_0, h2_0, c2_0, out);
}